// round 3
// baseline (speedup 1.0000x reference)
#include <cuda_runtime.h>
#include <cuda_bf16.h>
#include <cstdint>

// LightGCN propagation: N=100000 nodes, E=1600000 edges, D=64, L=3 layers.
// out = (x0 + x1 + x2 + x3) / 4 where x_{l+1} = A_norm @ x_l (with self loops).
//
// edge_index dtype is detected AT RUNTIME (int32 vs int64): JAX without x64
// silently demotes the reference's int64 to int32, and the element count
// (3,200,000) is identical either way. A device-side sampler disambiguates.

#define NN 100000
#define EE 1600000
#define DD 64
#define ND (NN * DD)      // 6,400,000 floats
#define ND4 (ND / 4)      // 1,600,000 float4

// Scratch (allocation-free: __device__ globals)
__device__ int g_is32;
__device__ int g_src[EE];
__device__ int g_dst[EE];
__device__ float g_deg[NN];
__device__ float g_dinv[NN];
__device__ float g_norm[EE];
__device__ float4 g_xA[ND4];
__device__ float4 g_xB[ND4];

// ---------------------------------------------------------------------------
// Index dtype detection + conversion
// ---------------------------------------------------------------------------
__global__ void k_detect(const void* __restrict__ idx) {
    if (threadIdx.x == 0 && blockIdx.x == 0) {
        const long long* p = (const long long*)idx;
        int is64 = 1;
        for (int i = 0; i < 256; i++) {
            long long v = p[i];
            if (v < 0 || v >= (long long)NN) { is64 = 0; break; }
        }
        g_is32 = !is64;
    }
}

__global__ __launch_bounds__(256) void k_convert(const void* __restrict__ idx) {
    int e = blockIdx.x * blockDim.x + threadIdx.x;
    if (e >= EE) return;
    if (g_is32) {
        const int* p = (const int*)idx;
        g_src[e] = p[e];
        g_dst[e] = p[EE + e];
    } else {
        const long long* p = (const long long*)idx;
        g_src[e] = (int)p[e];
        g_dst[e] = (int)p[EE + e];
    }
}

// ---------------------------------------------------------------------------
// Degree / norm precompute
// ---------------------------------------------------------------------------
__global__ __launch_bounds__(256) void k_deg_init() {
    int i = blockIdx.x * blockDim.x + threadIdx.x;
    if (i < NN) g_deg[i] = 1.0f;  // self-loop contributes 1 to every degree
}

__global__ __launch_bounds__(256) void k_deg_count() {
    int e = blockIdx.x * blockDim.x + threadIdx.x;
    if (e < EE) atomicAdd(&g_deg[g_src[e]], 1.0f);  // no return use -> RED
}

__global__ __launch_bounds__(256) void k_dinv() {
    int i = blockIdx.x * blockDim.x + threadIdx.x;
    if (i < NN) {
        float d = g_deg[i];
        g_dinv[i] = (d > 0.0f) ? rsqrtf(d) : 0.0f;
    }
}

__global__ __launch_bounds__(256) void k_norm(const float* __restrict__ w) {
    int e = blockIdx.x * blockDim.x + threadIdx.x;
    if (e < EE) g_norm[e] = g_dinv[g_src[e]] * w[e] * g_dinv[g_dst[e]];
}

// ---------------------------------------------------------------------------
// Per-layer kernels
// ---------------------------------------------------------------------------
// xNew = dinv^2 * xOld (self-loop term); out = xOld (accMode 0) or += xOld.
__global__ __launch_bounds__(256) void k_selfinit(const float4* __restrict__ xOld,
                                                  float4* __restrict__ xNew,
                                                  float4* __restrict__ out,
                                                  int accMode) {
    int i = blockIdx.x * blockDim.x + threadIdx.x;
    if (i >= ND4) return;
    int node = i >> 4;  // D/4 = 16 float4 per node
    float s = g_dinv[node];
    s = s * s;
    float4 v = xOld[i];
    xNew[i] = make_float4(s * v.x, s * v.y, s * v.z, s * v.w);
    if (accMode == 0) {
        out[i] = v;
    } else {
        float4 o = out[i];
        out[i] = make_float4(o.x + v.x, o.y + v.y, o.z + v.z, o.w + v.w);
    }
}

// Edge scatter: 16 threads per edge, one float4 each (full 256B row per edge,
// coalesced). Scatter via vectorized no-return reduction (red.global.add.v4).
__global__ __launch_bounds__(256) void k_scatter(const float4* __restrict__ xOld,
                                                 float* __restrict__ xNew) {
    long long t = (long long)blockIdx.x * blockDim.x + threadIdx.x;
    int e = (int)(t >> 4);
    int lane = (int)(t & 15);
    if (e >= EE) return;
    int src = g_src[e];
    int dst = g_dst[e];
    float nrm = g_norm[e];
    float4 v = __ldg(&xOld[src * 16 + lane]);
    float mx = nrm * v.x, my = nrm * v.y, mz = nrm * v.z, mw = nrm * v.w;
    float* p = xNew + (long long)dst * DD + lane * 4;
    asm volatile("red.global.add.v4.f32 [%0], {%1, %2, %3, %4};"
                 :: "l"(p), "f"(mx), "f"(my), "f"(mz), "f"(mw)
                 : "memory");
}

// Final: out = (out + xLast) * 0.25
__global__ __launch_bounds__(256) void k_final(const float4* __restrict__ xLast,
                                               float4* __restrict__ out) {
    int i = blockIdx.x * blockDim.x + threadIdx.x;
    if (i >= ND4) return;
    float4 o = out[i];
    float4 v = xLast[i];
    out[i] = make_float4((o.x + v.x) * 0.25f, (o.y + v.y) * 0.25f,
                         (o.z + v.z) * 0.25f, (o.w + v.w) * 0.25f);
}

// ---------------------------------------------------------------------------
extern "C" void kernel_launch(void* const* d_in, const int* in_sizes, int n_in,
                              void* d_out, int out_size) {
    // Bind inputs by unique element count (robust to metadata ordering).
    const float* emb = nullptr;   // 6,400,000 f32
    const float* ew = nullptr;    // 1,600,000 f32
    const void* idx = nullptr;    // 3,200,000 elems (int32 or int64 — detected)
    for (int i = 0; i < n_in; i++) {
        if (in_sizes[i] == ND) emb = (const float*)d_in[i];
        else if (in_sizes[i] == EE) ew = (const float*)d_in[i];
        else if (in_sizes[i] == 2 * EE) idx = d_in[i];
    }
    // Positional fallback (reference order: embedding, edge_weight, edge_index)
    if (!emb) emb = (const float*)d_in[0];
    if (!ew) ew = (const float*)d_in[1];
    if (!idx) idx = d_in[2];

    float4* out = (float4*)d_out;

    float4* xA;
    float4* xB;
    cudaGetSymbolAddress((void**)&xA, g_xA);
    cudaGetSymbolAddress((void**)&xB, g_xB);

    const int T = 256;
    const int gN = (NN + T - 1) / T;
    const int gE = (EE + T - 1) / T;
    const int gND4 = (ND4 + T - 1) / T;
    const int gScat = (int)(((long long)EE * 16 + T - 1) / T);

    const float4* embv = (const float4*)emb;

    // Index dtype detection + conversion to flat int32
    k_detect<<<1, 32>>>(idx);
    k_convert<<<gE, T>>>(idx);

    // Degrees and edge norms
    k_deg_init<<<gN, T>>>();
    k_deg_count<<<gE, T>>>();
    k_dinv<<<gN, T>>>();
    k_norm<<<gE, T>>>(ew);

    // Layer 1: x1 <- A @ emb ; out = emb
    k_selfinit<<<gND4, T>>>(embv, xB, out, 0);
    k_scatter<<<gScat, T>>>(embv, (float*)xB);

    // Layer 2: x2 <- A @ x1 ; out += x1
    k_selfinit<<<gND4, T>>>(xB, xA, out, 1);
    k_scatter<<<gScat, T>>>(xB, (float*)xA);

    // Layer 3: x3 <- A @ x2 ; out += x2
    k_selfinit<<<gND4, T>>>(xA, xB, out, 1);
    k_scatter<<<gScat, T>>>(xA, (float*)xB);

    // out = (out + x3) / 4
    k_final<<<gND4, T>>>(xB, out);
}

// round 4
// speedup vs baseline: 2.0027x; 2.0027x over previous
#include <cuda_runtime.h>
#include <cuda_bf16.h>
#include <cstdint>

// LightGCN propagation: N=100000, E=1600000, D=64, L=3.
// out = (x0 + x1 + x2 + x3)/4, x_{l+1} = A_norm @ x_l (with self loops).
//
// R4: pull-style CSR aggregation (no atomics in hot loop), fused self-loop /
// accumulation / final scaling into the per-layer kernel.

#define NN 100000
#define EE 1600000
#define DD 64
#define ND (NN * DD)       // 6,400,000 floats
#define ND4 (ND / 4)       // 1,600,000 float4
#define NB 391             // ceil(NN / 256)

// Scratch (allocation-free: __device__ globals)
__device__ int g_is32;
__device__ float g_deg[NN];      // source-occurrence degree (incl. self loop)
__device__ float g_dinv[NN];
__device__ int g_indeg[NN];      // destination in-degree (excl. self loop)
__device__ int g_part[NB];
__device__ int g_boff[NB];
__device__ int g_start[NN + 1];  // CSR row starts (by destination)
__device__ int g_cursor[NN];
__device__ uint2 g_csr[EE];      // packed (src, norm_bits), grouped by dst
__device__ float4 g_xA[ND4];
__device__ float4 g_xB[ND4];

// ---------------------------------------------------------------------------
// Init: degrees + index-dtype detection (JAX w/o x64 demotes int64 -> int32;
// element count is identical, so sample values to disambiguate).
// ---------------------------------------------------------------------------
__global__ __launch_bounds__(256) void k_init(const void* __restrict__ idx) {
    int i = blockIdx.x * blockDim.x + threadIdx.x;
    if (i < NN) {
        g_deg[i] = 1.0f;   // self loop contributes 1 to every degree
        g_indeg[i] = 0;
    }
    if (i == 0) {
        const long long* p = (const long long*)idx;
        int is64 = 1;
        for (int k = 0; k < 256; k++) {
            long long v = p[k];
            if (v < 0 || v >= (long long)NN) { is64 = 0; break; }
        }
        g_is32 = !is64;
    }
}

__global__ __launch_bounds__(256) void k_count(const void* __restrict__ idx) {
    int e = blockIdx.x * blockDim.x + threadIdx.x;
    if (e >= EE) return;
    int src, dst;
    if (g_is32) {
        const int* p = (const int*)idx;
        src = p[e]; dst = p[EE + e];
    } else {
        const long long* p = (const long long*)idx;
        src = (int)p[e]; dst = (int)p[EE + e];
    }
    atomicAdd(&g_deg[src], 1.0f);
    atomicAdd(&g_indeg[dst], 1);
}

__global__ __launch_bounds__(256) void k_dinv() {
    int i = blockIdx.x * blockDim.x + threadIdx.x;
    if (i < NN) {
        float d = g_deg[i];
        g_dinv[i] = (d > 0.0f) ? rsqrtf(d) : 0.0f;
    }
}

// ---------------------------------------------------------------------------
// Exclusive scan of in-degrees -> CSR starts (3-kernel hierarchy)
// ---------------------------------------------------------------------------
__global__ __launch_bounds__(256) void k_scan1() {
    __shared__ int sh[256];
    int i = blockIdx.x * 256 + threadIdx.x;
    sh[threadIdx.x] = (i < NN) ? g_indeg[i] : 0;
    __syncthreads();
    for (int s = 128; s > 0; s >>= 1) {
        if (threadIdx.x < s) sh[threadIdx.x] += sh[threadIdx.x + s];
        __syncthreads();
    }
    if (threadIdx.x == 0) g_part[blockIdx.x] = sh[0];
}

__global__ __launch_bounds__(512) void k_scan2() {
    __shared__ int sh[512];
    int t = threadIdx.x;
    sh[t] = (t < NB) ? g_part[t] : 0;
    __syncthreads();
    for (int off = 1; off < 512; off <<= 1) {
        int v = (t >= off) ? sh[t - off] : 0;
        __syncthreads();
        sh[t] += v;
        __syncthreads();
    }
    if (t < NB) g_boff[t] = (t == 0) ? 0 : sh[t - 1];
}

__global__ __launch_bounds__(256) void k_scan3() {
    __shared__ int sh[256];
    int i = blockIdx.x * 256 + threadIdx.x;
    int v = (i < NN) ? g_indeg[i] : 0;
    sh[threadIdx.x] = v;
    __syncthreads();
    for (int off = 1; off < 256; off <<= 1) {
        int t = (threadIdx.x >= off) ? sh[threadIdx.x - off] : 0;
        __syncthreads();
        sh[threadIdx.x] += t;
        __syncthreads();
    }
    if (i < NN) {
        int excl = g_boff[blockIdx.x] + sh[threadIdx.x] - v;
        g_start[i] = excl;
        g_cursor[i] = excl;
        if (i == NN - 1) g_start[NN] = excl + v;
    }
}

// Fill CSR: compute edge norm, place (src, norm) into destination's bucket.
__global__ __launch_bounds__(256) void k_fill(const void* __restrict__ idx,
                                              const float* __restrict__ w) {
    int e = blockIdx.x * blockDim.x + threadIdx.x;
    if (e >= EE) return;
    int src, dst;
    if (g_is32) {
        const int* p = (const int*)idx;
        src = p[e]; dst = p[EE + e];
    } else {
        const long long* p = (const long long*)idx;
        src = (int)p[e]; dst = (int)p[EE + e];
    }
    float nrm = g_dinv[src] * w[e] * g_dinv[dst];
    int pos = atomicAdd(&g_cursor[dst], 1);
    g_csr[pos] = make_uint2((unsigned)src, __float_as_uint(nrm));
}

// ---------------------------------------------------------------------------
// Layer kernel: 16-lane group per node, one float4 column per lane.
//   acc = dinv[n]^2 * xOld[n] + sum_{e in CSR[n]} norm[e] * xOld[src[e]]
// mode 0: out = xOld;  xNew = acc           (layer 1)
// mode 1: out += xOld; xNew = acc           (layer 2)
// mode 2: out = (out + xOld + acc) * 0.25   (layer 3, skips xNew write)
// ---------------------------------------------------------------------------
__global__ __launch_bounds__(256) void k_layer(const float4* __restrict__ xOld,
                                               float4* __restrict__ xNew,
                                               float4* __restrict__ out,
                                               int mode) {
    int tid = threadIdx.x;
    int lane = tid & 15;
    int node = blockIdx.x * 16 + (tid >> 4);   // grid covers exactly NN
    unsigned mask = 0xFFFFu << (tid & 16);     // this half-warp's lanes

    int start = g_start[node];
    int end = g_start[node + 1];
    float s = g_dinv[node];
    s *= s;

    int o = node * 16 + lane;
    float4 v0 = xOld[o];
    float ax = s * v0.x, ay = s * v0.y, az = s * v0.z, aw = s * v0.w;

    for (int base = start; base < end; base += 16) {
        int e = base + lane;
        uint2 ed = (e < end) ? g_csr[e] : make_uint2(0u, 0u);
        int m = end - base;
        if (m > 16) m = 16;
        for (int j = 0; j < m; j++) {
            unsigned sj = __shfl_sync(mask, ed.x, j, 16);
            unsigned nj = __shfl_sync(mask, ed.y, j, 16);
            float nf = __uint_as_float(nj);
            float4 v = __ldg(&xOld[sj * 16 + lane]);
            ax = fmaf(nf, v.x, ax);
            ay = fmaf(nf, v.y, ay);
            az = fmaf(nf, v.z, az);
            aw = fmaf(nf, v.w, aw);
        }
    }

    if (mode == 0) {
        out[o] = v0;
        xNew[o] = make_float4(ax, ay, az, aw);
    } else if (mode == 1) {
        float4 t = out[o];
        out[o] = make_float4(t.x + v0.x, t.y + v0.y, t.z + v0.z, t.w + v0.w);
        xNew[o] = make_float4(ax, ay, az, aw);
    } else {
        float4 t = out[o];
        out[o] = make_float4((t.x + v0.x + ax) * 0.25f,
                             (t.y + v0.y + ay) * 0.25f,
                             (t.z + v0.z + az) * 0.25f,
                             (t.w + v0.w + aw) * 0.25f);
    }
}

// ---------------------------------------------------------------------------
extern "C" void kernel_launch(void* const* d_in, const int* in_sizes, int n_in,
                              void* d_out, int out_size) {
    // Bind inputs by unique element count (robust to metadata ordering).
    const float* emb = nullptr;   // 6,400,000 f32
    const float* ew = nullptr;    // 1,600,000 f32
    const void* idx = nullptr;    // 3,200,000 elems (int32 or int64, detected)
    for (int i = 0; i < n_in; i++) {
        if (in_sizes[i] == ND) emb = (const float*)d_in[i];
        else if (in_sizes[i] == EE) ew = (const float*)d_in[i];
        else if (in_sizes[i] == 2 * EE) idx = d_in[i];
    }
    if (!emb) emb = (const float*)d_in[0];
    if (!ew) ew = (const float*)d_in[1];
    if (!idx) idx = d_in[2];

    float4* out = (float4*)d_out;
    float4* xA;
    float4* xB;
    cudaGetSymbolAddress((void**)&xA, g_xA);
    cudaGetSymbolAddress((void**)&xB, g_xB);

    const int T = 256;
    const int gN = (NN + T - 1) / T;       // 391
    const int gE = (EE + T - 1) / T;       // 6250
    const int gL = NN / 16;                // 6250 (exact)

    const float4* embv = (const float4*)emb;

    // Precompute: degrees, dinv, CSR
    k_init<<<gN, T>>>(idx);
    k_count<<<gE, T>>>(idx);
    k_dinv<<<gN, T>>>();
    k_scan1<<<NB, T>>>();
    k_scan2<<<1, 512>>>();
    k_scan3<<<NB, T>>>();
    k_fill<<<gE, T>>>(idx, ew);

    // Layer 1: x1 <- A @ x0 ; out = x0
    k_layer<<<gL, T>>>(embv, xB, out, 0);
    // Layer 2: x2 <- A @ x1 ; out += x1
    k_layer<<<gL, T>>>(xB, xA, out, 1);
    // Layer 3: x3 <- A @ x2 ; out = (out + x2 + x3)/4
    k_layer<<<gL, T>>>(xA, nullptr, out, 2);
}